// round 7
// baseline (speedup 1.0000x reference)
#include <cuda_runtime.h>

#define V_VOCAB 500000
#define D 128
#define M_MEM 1000
#define L_MEM 64
#define L_X 64
#define C_N 100
#define L_C 32
#define L_Y 32
#define N_SLOTS (M_MEM + 1)           /* 1001 partials: 0..999 mems, 1000 xs */
#define OUT_ROWS (1 + C_N)            /* 101 */
#define MAX_NORM 10.0f
#define RENORM_EPS 1e-7f
#define COS_EPS 1e-8f

// xs encoding (the only encoding that must be globally visible).
__device__ float g_enc_x[D];
// Per-row partials: g_part[slot] = exp(sim_slot) * enc_slot ; g_psum[slot] = exp(sim_slot)
__device__ float g_part[(size_t)N_SLOTS * D];
__device__ float g_psum[N_SLOTS];
// Sync state (zero-initialized at load; reset by the finalizer every launch).
__device__ int g_flag;
__device__ int g_counter;

// ---------------------------------------------------------------------------
// Encode body, L compile-time. 512 threads = 16 warps; warp w owns tokens
// w, w+16, ... Gathers all in flight, interleaved norm reduces.
// Returns the encoding component for tid < D (garbage otherwise); writes to
// dst if dst != nullptr.
// ---------------------------------------------------------------------------
template <int L>
__device__ __forceinline__ float encode_body(
    const int* __restrict__ seq,
    const float* __restrict__ lt, const float* __restrict__ freqs,
    float* __restrict__ dst)
{
    constexpr int NW = 16;
    constexpr int NT = L / NW;

    __shared__ int   sh_idx[L];
    __shared__ float sh_w[L];
    __shared__ float sh_wred[2];
    __shared__ float sh_acc[NW][D];

    int tid  = threadIdx.x;
    int warp = tid >> 5;
    int lane = tid & 31;

    if (tid < L) {
        int idx = seq[tid];
        sh_idx[tid] = idx;
        float f = freqs[idx];
        sh_w[tid] = f;
        float ws = f * f;
        #pragma unroll
        for (int o = 16; o > 0; o >>= 1)
            ws += __shfl_xor_sync(0xffffffffu, ws, o);
        if (lane == 0) sh_wred[warp] = ws;
    }
    __syncthreads();

    float inv_wnorm = rsqrtf((L > 32) ? (sh_wred[0] + sh_wred[1]) : sh_wred[0]);

    float4 e[NT];
    int    tok[NT];
    #pragma unroll
    for (int k = 0; k < NT; k++) {
        tok[k] = warp + NW * k;
        int idx = sh_idx[tok[k]];
        e[k] = *reinterpret_cast<const float4*>(lt + (size_t)idx * D + lane * 4);
    }

    float sq[NT];
    #pragma unroll
    for (int k = 0; k < NT; k++)
        sq[k] = e[k].x * e[k].x + e[k].y * e[k].y
              + e[k].z * e[k].z + e[k].w * e[k].w;
    #pragma unroll
    for (int o = 16; o > 0; o >>= 1) {
        #pragma unroll
        for (int k = 0; k < NT; k++)
            sq[k] += __shfl_xor_sync(0xffffffffu, sq[k], o);
    }

    float4 acc = make_float4(0.0f, 0.0f, 0.0f, 0.0f);
    #pragma unroll
    for (int k = 0; k < NT; k++) {
        float n = sqrtf(sq[k]);
        float scale = (n > MAX_NORM) ? (MAX_NORM / (n + RENORM_EPS)) : 1.0f;
        float wl = sh_w[tok[k]] * inv_wnorm * scale;
        acc.x += wl * e[k].x;
        acc.y += wl * e[k].y;
        acc.z += wl * e[k].z;
        acc.w += wl * e[k].w;
    }

    sh_acc[warp][lane * 4 + 0] = acc.x;
    sh_acc[warp][lane * 4 + 1] = acc.y;
    sh_acc[warp][lane * 4 + 2] = acc.z;
    sh_acc[warp][lane * 4 + 3] = acc.w;
    __syncthreads();

    float s = 0.0f;
    if (tid < D) {
        #pragma unroll
        for (int w = 0; w < NW; w++) s += sh_acc[w][tid];
        if (dst) dst[tid] = s;
    }
    return s;
}

// ---------------------------------------------------------------------------
// Single fused kernel.
//   b == 0          : encode xs -> g_enc_x, raise flag, contribute slot 1000
//   b in 1..1000    : encode mem (registers only), wait flag, contribute slot b-1
//   b == 1001       : encode ys -> out row OUT_ROWS (independent)
//   b >= 1002       : encode cand -> out rows OUT_ROWS+1.. (independent)
// Last of the 1001 contributing blocks reduces the partials and writes the
// broadcast lhs rows, then resets flag/counter for the next graph replay.
// ---------------------------------------------------------------------------
__global__ __launch_bounds__(512) void fused_kernel(
    const int* __restrict__ xs, const int* __restrict__ mems,
    const int* __restrict__ ys, const int* __restrict__ cands,
    const float* __restrict__ lt, const float* __restrict__ freqs,
    float* __restrict__ out)
{
    int b   = blockIdx.x;
    int tid = threadIdx.x;
    int warp = tid >> 5;
    int lane = tid & 31;

    // --- independent output encodings ---
    if (b == M_MEM + 1) {
        encode_body<L_Y>(ys, lt, freqs, out + (size_t)OUT_ROWS * D);
        return;
    }
    if (b > M_MEM + 1) {
        int c = b - M_MEM - 2;
        encode_body<L_C>(cands + (size_t)c * L_C, lt, freqs,
                         out + (size_t)(OUT_ROWS + 1 + c) * D);
        return;
    }

    // --- contributing blocks (xs + mems) ---
    float s;
    if (b == 0) {
        s = encode_body<L_X>(xs, lt, freqs, g_enc_x);
        __syncthreads();
        if (tid == 0) {
            __threadfence();
            atomicExch(&g_flag, 1);
        }
    } else {
        s = encode_body<L_MEM>(mems + (size_t)(b - 1) * L_MEM, lt, freqs, nullptr);
        if (tid == 0) {
            while (atomicAdd(&g_flag, 0) == 0) __nanosleep(64);
            __threadfence();
        }
        __syncthreads();
    }

    // --- cosine sim of s vs x, block reduce over the 4 low warps ---
    __shared__ float red3[4][3];
    __shared__ float sh_ex;

    float x = 0.0f;
    if (tid < D) x = __ldcg(&g_enc_x[tid]);

    if (tid < D) {
        float pd = s * x, ps = s * s, px = x * x;
        #pragma unroll
        for (int o = 16; o > 0; o >>= 1) {
            pd += __shfl_xor_sync(0xffffffffu, pd, o);
            ps += __shfl_xor_sync(0xffffffffu, ps, o);
            px += __shfl_xor_sync(0xffffffffu, px, o);
        }
        if (lane == 0) {
            red3[warp][0] = pd;
            red3[warp][1] = ps;
            red3[warp][2] = px;
        }
    }
    __syncthreads();
    if (tid == 0) {
        float dot = red3[0][0] + red3[1][0] + red3[2][0] + red3[3][0];
        float ssq = red3[0][1] + red3[1][1] + red3[2][1] + red3[3][1];
        float xsq = red3[0][2] + red3[1][2] + red3[2][2] + red3[3][2];
        float nx = fmaxf(sqrtf(xsq), COS_EPS);
        float nm = fmaxf(sqrtf(ssq), COS_EPS);
        sh_ex = expf(dot / (nx * nm));   // cosines in [-1,1]: exp safe, no max shift
    }
    __syncthreads();
    float ex = sh_ex;

    int slot = (b == 0) ? M_MEM : (b - 1);
    if (tid < D) g_part[(size_t)slot * D + tid] = ex * s;
    if (tid == 0) g_psum[slot] = ex;
    __threadfence();
    __syncthreads();

    // --- count arrivals; last block finalizes ---
    __shared__ int sh_last;
    if (tid == 0) {
        int old = atomicAdd(&g_counter, 1);
        sh_last = (old == M_MEM) ? 1 : 0;
    }
    __syncthreads();
    if (!sh_last) return;
    __threadfence();

    // --- finalize: fixed-order reduce of 1001 partials ---
    __shared__ float cpart[16][D];
    __shared__ float csum[32];
    __shared__ float sh_tot;
    __shared__ float sh_lhs[D];

    {
        int q = tid & 31;          // float4 column
        int chunk = tid >> 5;      // 0..15
        float4 acc = make_float4(0.0f, 0.0f, 0.0f, 0.0f);
        for (int i = chunk; i < N_SLOTS; i += 16) {
            const float* p = &g_part[(size_t)i * D + q * 4];
            float4 v = make_float4(__ldcg(p + 0), __ldcg(p + 1),
                                   __ldcg(p + 2), __ldcg(p + 3));
            acc.x += v.x; acc.y += v.y; acc.z += v.z; acc.w += v.w;
        }
        cpart[chunk][q * 4 + 0] = acc.x;
        cpart[chunk][q * 4 + 1] = acc.y;
        cpart[chunk][q * 4 + 2] = acc.z;
        cpart[chunk][q * 4 + 3] = acc.w;
    }
    if (warp == 0) {
        float sm = 0.0f;
        for (int i = lane; i < N_SLOTS; i += 32) sm += __ldcg(&g_psum[i]);
        #pragma unroll
        for (int o = 16; o > 0; o >>= 1)
            sm += __shfl_xor_sync(0xffffffffu, sm, o);
        if (lane == 0) sh_tot = sm;
    }
    __syncthreads();

    if (tid < D) {
        float sum = 0.0f;
        #pragma unroll
        for (int c = 0; c < 16; c++) sum += cpart[c][tid];
        sh_lhs[tid] = sum / sh_tot;
    }
    __syncthreads();

    for (int j = tid; j < OUT_ROWS * D; j += 512)
        out[j] = sh_lhs[j & (D - 1)];

    // reset sync state for the next graph replay
    if (tid == 0) {
        g_counter = 0;
        g_flag = 0;
    }
}

extern "C" void kernel_launch(void* const* d_in, const int* in_sizes, int n_in,
                              void* d_out, int out_size) {
    const int*   xs    = (const int*)d_in[0];
    const int*   mems  = (const int*)d_in[1];
    const int*   ys    = (const int*)d_in[2];
    const int*   cands = (const int*)d_in[3];
    const float* lt    = (const float*)d_in[4];
    const float* freqs = (const float*)d_in[5];
    float* out = (float*)d_out;

    fused_kernel<<<2 + M_MEM + C_N, 512>>>(xs, mems, ys, cands, lt, freqs, out);
}

// round 8
// speedup vs baseline: 1.4908x; 1.4908x over previous
#include <cuda_runtime.h>

#define V_VOCAB 500000
#define D 128
#define M_MEM 1000
#define L_MEM 64
#define L_X 64
#define C_N 100
#define L_C 32
#define L_Y 32
#define N_MEMS (M_MEM + 1)            /* 1001: row0=xs, rows1..1000=mems */
#define OUT_ROWS (1 + C_N)            /* 101 */
#define NBLK_B 126                    /* ceil(1001/8) */
#define MAX_NORM 10.0f
#define RENORM_EPS 1e-7f
#define COS_EPS 1e-8f

// row 0 = xs encoding, rows 1..1000 = mems encodings. 512.5 KB.
__device__ float g_enc[(size_t)N_MEMS * D];
// per-block partials from kernel B
__device__ float g_part[(size_t)NBLK_B * D];
__device__ float g_psum[NBLK_B];
__device__ int   g_counter;          // zero-init; reset by finalizing block

// ---------------------------------------------------------------------------
// Encode body, L compile-time. 512 threads = 16 warps; warp w owns tokens
// w, w+16, ... All gathers in flight; norm reduces interleaved.
// ---------------------------------------------------------------------------
template <int L>
__device__ __forceinline__ void encode_body(
    const int* __restrict__ seq,
    const float* __restrict__ lt, const float* __restrict__ freqs,
    float* __restrict__ dst)
{
    constexpr int NW = 16;
    constexpr int NT = L / NW;

    __shared__ int   sh_idx[L];
    __shared__ float sh_w[L];
    __shared__ float sh_wred[2];
    __shared__ float sh_acc[NW][D];

    int tid  = threadIdx.x;
    int warp = tid >> 5;
    int lane = tid & 31;

    if (tid < L) {
        int idx = seq[tid];
        sh_idx[tid] = idx;
        float f = freqs[idx];
        sh_w[tid] = f;
        float ws = f * f;
        #pragma unroll
        for (int o = 16; o > 0; o >>= 1)
            ws += __shfl_xor_sync(0xffffffffu, ws, o);
        if (lane == 0) sh_wred[warp] = ws;
    }
    __syncthreads();

    float inv_wnorm = rsqrtf((L > 32) ? (sh_wred[0] + sh_wred[1]) : sh_wred[0]);

    float4 e[NT];
    int    tok[NT];
    #pragma unroll
    for (int k = 0; k < NT; k++) {
        tok[k] = warp + NW * k;
        int idx = sh_idx[tok[k]];
        e[k] = *reinterpret_cast<const float4*>(lt + (size_t)idx * D + lane * 4);
    }

    float sq[NT];
    #pragma unroll
    for (int k = 0; k < NT; k++)
        sq[k] = e[k].x * e[k].x + e[k].y * e[k].y
              + e[k].z * e[k].z + e[k].w * e[k].w;
    #pragma unroll
    for (int o = 16; o > 0; o >>= 1) {
        #pragma unroll
        for (int k = 0; k < NT; k++)
            sq[k] += __shfl_xor_sync(0xffffffffu, sq[k], o);
    }

    float4 acc = make_float4(0.0f, 0.0f, 0.0f, 0.0f);
    #pragma unroll
    for (int k = 0; k < NT; k++) {
        float n = sqrtf(sq[k]);
        float scale = (n > MAX_NORM) ? (MAX_NORM / (n + RENORM_EPS)) : 1.0f;
        float wl = sh_w[tok[k]] * inv_wnorm * scale;
        acc.x += wl * e[k].x;
        acc.y += wl * e[k].y;
        acc.z += wl * e[k].z;
        acc.w += wl * e[k].w;
    }

    sh_acc[warp][lane * 4 + 0] = acc.x;
    sh_acc[warp][lane * 4 + 1] = acc.y;
    sh_acc[warp][lane * 4 + 2] = acc.z;
    sh_acc[warp][lane * 4 + 3] = acc.w;
    __syncthreads();

    if (tid < D) {
        float s = 0.0f;
        #pragma unroll
        for (int w = 0; w < NW; w++) s += sh_acc[w][tid];
        dst[tid] = s;
    }
}

// ---------------------------------------------------------------------------
// Kernel A: encode all 1102 sequences (fully independent).
// ---------------------------------------------------------------------------
__global__ __launch_bounds__(512) void encode_all(
    const int* __restrict__ xs, const int* __restrict__ mems,
    const int* __restrict__ ys, const int* __restrict__ cands,
    const float* __restrict__ lt, const float* __restrict__ freqs,
    float* __restrict__ out)
{
    int b = blockIdx.x;
    if (b == 0) {
        encode_body<L_X>(xs, lt, freqs, g_enc);
    } else if (b <= M_MEM) {
        encode_body<L_MEM>(mems + (size_t)(b - 1) * L_MEM, lt, freqs,
                           g_enc + (size_t)b * D);
    } else if (b == M_MEM + 1) {
        encode_body<L_Y>(ys, lt, freqs, out + (size_t)OUT_ROWS * D);
    } else {
        int c = b - M_MEM - 2;
        encode_body<L_C>(cands + (size_t)c * L_C, lt, freqs,
                         out + (size_t)(OUT_ROWS + 1 + c) * D);
    }
}

// ---------------------------------------------------------------------------
// Kernel B: sims + exp + per-block partials; the LAST block (atomic counter)
// reduces the 126 partials in fixed order and writes the broadcast output.
// 126 blocks x 8 warps, one row per warp. exp needs no max shift: cosines
// are in [-1,1].
// ---------------------------------------------------------------------------
__global__ __launch_bounds__(256) void sims_finalize_kernel(float* __restrict__ out)
{
    __shared__ float sh_part[8][D];
    __shared__ float sh_exp[8];

    int tid  = threadIdx.x;
    int warp = tid >> 5;
    int lane = tid & 31;
    int i = blockIdx.x * 8 + warp;
    bool valid = (i < N_MEMS);
    int r = valid ? ((i < M_MEM) ? (i + 1) : 0) : 0;

    float4 x = *reinterpret_cast<const float4*>(&g_enc[lane * 4]);
    float4 e = *reinterpret_cast<const float4*>(&g_enc[(size_t)r * D + lane * 4]);

    float dot = e.x * x.x + e.y * x.y + e.z * x.z + e.w * x.w;
    float esq = e.x * e.x + e.y * e.y + e.z * e.z + e.w * e.w;
    float xsq = x.x * x.x + x.y * x.y + x.z * x.z + x.w * x.w;
    #pragma unroll
    for (int o = 16; o > 0; o >>= 1) {
        dot += __shfl_xor_sync(0xffffffffu, dot, o);
        esq += __shfl_xor_sync(0xffffffffu, esq, o);
        xsq += __shfl_xor_sync(0xffffffffu, xsq, o);
    }
    float nx = fmaxf(sqrtf(xsq), COS_EPS);
    float nm = fmaxf(sqrtf(esq), COS_EPS);
    float ex = valid ? expf(dot / (nx * nm)) : 0.0f;

    sh_part[warp][lane * 4 + 0] = ex * e.x;
    sh_part[warp][lane * 4 + 1] = ex * e.y;
    sh_part[warp][lane * 4 + 2] = ex * e.z;
    sh_part[warp][lane * 4 + 3] = ex * e.w;
    if (lane == 0) sh_exp[warp] = ex;
    __syncthreads();

    if (tid < D) {
        float s = 0.0f;
        #pragma unroll
        for (int w = 0; w < 8; w++) s += sh_part[w][tid];
        g_part[(size_t)blockIdx.x * D + tid] = s;
    }
    if (tid == 0) {
        float s = 0.0f;
        #pragma unroll
        for (int w = 0; w < 8; w++) s += sh_exp[w];
        g_psum[blockIdx.x] = s;
    }
    __threadfence();
    __syncthreads();

    // --- last block finalizes ---
    __shared__ int sh_last;
    if (tid == 0) {
        int old = atomicAdd(&g_counter, 1);
        sh_last = (old == NBLK_B - 1) ? 1 : 0;
    }
    __syncthreads();
    if (!sh_last) return;
    __threadfence();

    __shared__ float cpart[8][D];
    __shared__ float sh_tot;
    __shared__ float sh_lhs[D];

    {
        int q = tid & 31;          // float4 column
        int chunk = tid >> 5;      // 0..7
        float4 acc = make_float4(0.0f, 0.0f, 0.0f, 0.0f);
        for (int bb = chunk; bb < NBLK_B; bb += 8) {
            const float* p = &g_part[(size_t)bb * D + q * 4];
            acc.x += __ldcg(p + 0);
            acc.y += __ldcg(p + 1);
            acc.z += __ldcg(p + 2);
            acc.w += __ldcg(p + 3);
        }
        cpart[chunk][q * 4 + 0] = acc.x;
        cpart[chunk][q * 4 + 1] = acc.y;
        cpart[chunk][q * 4 + 2] = acc.z;
        cpart[chunk][q * 4 + 3] = acc.w;
    }
    if (warp == 0) {
        float sm = 0.0f;
        for (int bb = lane; bb < NBLK_B; bb += 32) sm += __ldcg(&g_psum[bb]);
        #pragma unroll
        for (int o = 16; o > 0; o >>= 1)
            sm += __shfl_xor_sync(0xffffffffu, sm, o);
        if (lane == 0) sh_tot = sm;
    }
    __syncthreads();

    if (tid < D) {
        float s = 0.0f;
        #pragma unroll
        for (int c = 0; c < 8; c++) s += cpart[c][tid];
        sh_lhs[tid] = s / sh_tot;
    }
    __syncthreads();

    for (int j = tid; j < OUT_ROWS * D; j += 256)
        out[j] = sh_lhs[j & (D - 1)];

    if (tid == 0) g_counter = 0;   // reset for next graph replay
}

extern "C" void kernel_launch(void* const* d_in, const int* in_sizes, int n_in,
                              void* d_out, int out_size) {
    const int*   xs    = (const int*)d_in[0];
    const int*   mems  = (const int*)d_in[1];
    const int*   ys    = (const int*)d_in[2];
    const int*   cands = (const int*)d_in[3];
    const float* lt    = (const float*)d_in[4];
    const float* freqs = (const float*)d_in[5];
    float* out = (float*)d_out;

    encode_all<<<2 + M_MEM + C_N, 512>>>(xs, mems, ys, cands, lt, freqs, out);
    sims_finalize_kernel<<<NBLK_B, 256>>>(out);
}

// round 9
// speedup vs baseline: 1.7890x; 1.2000x over previous
#include <cuda_runtime.h>

#define V_VOCAB 500000
#define D 128
#define M_MEM 1000
#define L_MEM 64
#define L_X 64
#define C_N 100
#define L_C 32
#define L_Y 32
#define N_MEMS (M_MEM + 1)            /* 1001: row0=xs, rows1..1000=mems */
#define OUT_ROWS (1 + C_N)            /* 101 */
#define NBLK_B 63                     /* ceil(1001/16) */
#define MAX_NORM 10.0f
#define RENORM_EPS 1e-7f
#define COS_EPS 1e-8f

// row 0 = xs encoding, rows 1..1000 = mems encodings. 512.5 KB.
__device__ float g_enc[(size_t)N_MEMS * D];
// per-block partials from kernel B
__device__ float g_part[(size_t)NBLK_B * D];
__device__ float g_psum[NBLK_B];
__device__ int   g_counter;          // zero-init; reset by finalizing block

// ---------------------------------------------------------------------------
// Encode body, L compile-time. 512 threads = 16 warps; warp w owns tokens
// w, w+16, ... All gathers in flight; norm reduces interleaved.
// ---------------------------------------------------------------------------
template <int L>
__device__ __forceinline__ void encode_body(
    const int* __restrict__ seq,
    const float* __restrict__ lt, const float* __restrict__ freqs,
    float* __restrict__ dst)
{
    constexpr int NW = 16;
    constexpr int NT = L / NW;

    __shared__ int   sh_idx[L];
    __shared__ float sh_w[L];
    __shared__ float sh_wred[2];
    __shared__ float sh_acc[NW][D];

    int tid  = threadIdx.x;
    int warp = tid >> 5;
    int lane = tid & 31;

    if (tid < L) {
        int idx = seq[tid];
        sh_idx[tid] = idx;
        float f = freqs[idx];
        sh_w[tid] = f;
        float ws = f * f;
        #pragma unroll
        for (int o = 16; o > 0; o >>= 1)
            ws += __shfl_xor_sync(0xffffffffu, ws, o);
        if (lane == 0) sh_wred[warp] = ws;
    }
    __syncthreads();

    float inv_wnorm = rsqrtf((L > 32) ? (sh_wred[0] + sh_wred[1]) : sh_wred[0]);

    float4 e[NT];
    int    tok[NT];
    #pragma unroll
    for (int k = 0; k < NT; k++) {
        tok[k] = warp + NW * k;
        int idx = sh_idx[tok[k]];
        e[k] = *reinterpret_cast<const float4*>(lt + (size_t)idx * D + lane * 4);
    }

    float sq[NT];
    #pragma unroll
    for (int k = 0; k < NT; k++)
        sq[k] = e[k].x * e[k].x + e[k].y * e[k].y
              + e[k].z * e[k].z + e[k].w * e[k].w;
    #pragma unroll
    for (int o = 16; o > 0; o >>= 1) {
        #pragma unroll
        for (int k = 0; k < NT; k++)
            sq[k] += __shfl_xor_sync(0xffffffffu, sq[k], o);
    }

    float4 acc = make_float4(0.0f, 0.0f, 0.0f, 0.0f);
    #pragma unroll
    for (int k = 0; k < NT; k++) {
        float n = sqrtf(sq[k]);
        float scale = (n > MAX_NORM) ? (MAX_NORM / (n + RENORM_EPS)) : 1.0f;
        float wl = sh_w[tok[k]] * inv_wnorm * scale;
        acc.x += wl * e[k].x;
        acc.y += wl * e[k].y;
        acc.z += wl * e[k].z;
        acc.w += wl * e[k].w;
    }

    sh_acc[warp][lane * 4 + 0] = acc.x;
    sh_acc[warp][lane * 4 + 1] = acc.y;
    sh_acc[warp][lane * 4 + 2] = acc.z;
    sh_acc[warp][lane * 4 + 3] = acc.w;
    __syncthreads();

    if (tid < D) {
        float s = 0.0f;
        #pragma unroll
        for (int w = 0; w < NW; w++) s += sh_acc[w][tid];
        dst[tid] = s;
    }
}

// ---------------------------------------------------------------------------
// Kernel A: encode all 1102 sequences (fully independent).
// ---------------------------------------------------------------------------
__global__ __launch_bounds__(512) void encode_all(
    const int* __restrict__ xs, const int* __restrict__ mems,
    const int* __restrict__ ys, const int* __restrict__ cands,
    const float* __restrict__ lt, const float* __restrict__ freqs,
    float* __restrict__ out)
{
    int b = blockIdx.x;
    if (b == 0) {
        encode_body<L_X>(xs, lt, freqs, g_enc);
    } else if (b <= M_MEM) {
        encode_body<L_MEM>(mems + (size_t)(b - 1) * L_MEM, lt, freqs,
                           g_enc + (size_t)b * D);
    } else if (b == M_MEM + 1) {
        encode_body<L_Y>(ys, lt, freqs, out + (size_t)OUT_ROWS * D);
    } else {
        int c = b - M_MEM - 2;
        encode_body<L_C>(cands + (size_t)c * L_C, lt, freqs,
                         out + (size_t)(OUT_ROWS + 1 + c) * D);
    }
}

// ---------------------------------------------------------------------------
// Kernel B: sims + exp + per-block partials; the LAST block (atomic counter)
// reduces the 63 partials in fixed order and writes the broadcast output.
// 63 blocks x 16 warps, one row per warp. exp needs no max shift: cosines
// are in [-1,1].
// ---------------------------------------------------------------------------
__global__ __launch_bounds__(512) void sims_finalize_kernel(float* __restrict__ out)
{
    __shared__ float sh_part[16][D];
    __shared__ float sh_exp[16];

    int tid  = threadIdx.x;
    int warp = tid >> 5;
    int lane = tid & 31;
    int i = blockIdx.x * 16 + warp;
    bool valid = (i < N_MEMS);
    int r = valid ? ((i < M_MEM) ? (i + 1) : 0) : 0;

    float4 x = *reinterpret_cast<const float4*>(&g_enc[lane * 4]);
    float4 e = *reinterpret_cast<const float4*>(&g_enc[(size_t)r * D + lane * 4]);

    float dot = e.x * x.x + e.y * x.y + e.z * x.z + e.w * x.w;
    float esq = e.x * e.x + e.y * e.y + e.z * e.z + e.w * e.w;
    float xsq = x.x * x.x + x.y * x.y + x.z * x.z + x.w * x.w;
    #pragma unroll
    for (int o = 16; o > 0; o >>= 1) {
        dot += __shfl_xor_sync(0xffffffffu, dot, o);
        esq += __shfl_xor_sync(0xffffffffu, esq, o);
        xsq += __shfl_xor_sync(0xffffffffu, xsq, o);
    }
    float nx = fmaxf(sqrtf(xsq), COS_EPS);
    float nm = fmaxf(sqrtf(esq), COS_EPS);
    float ex = valid ? expf(dot / (nx * nm)) : 0.0f;

    sh_part[warp][lane * 4 + 0] = ex * e.x;
    sh_part[warp][lane * 4 + 1] = ex * e.y;
    sh_part[warp][lane * 4 + 2] = ex * e.z;
    sh_part[warp][lane * 4 + 3] = ex * e.w;
    if (lane == 0) sh_exp[warp] = ex;
    __syncthreads();

    if (tid < D) {
        float s = 0.0f;
        #pragma unroll
        for (int w = 0; w < 16; w++) s += sh_part[w][tid];
        g_part[(size_t)blockIdx.x * D + tid] = s;
    }
    if (tid == 0) {
        float s = 0.0f;
        #pragma unroll
        for (int w = 0; w < 16; w++) s += sh_exp[w];
        g_psum[blockIdx.x] = s;
    }
    __threadfence();
    __syncthreads();

    // --- last block finalizes ---
    __shared__ int sh_last;
    if (tid == 0) {
        int old = atomicAdd(&g_counter, 1);
        sh_last = (old == NBLK_B - 1) ? 1 : 0;
    }
    __syncthreads();
    if (!sh_last) return;
    __threadfence();

    __shared__ float cpart[16][D];
    __shared__ float sh_tot;
    __shared__ float sh_lhs[D];

    {
        int q = tid & 31;          // float4 column
        int chunk = tid >> 5;      // 0..15
        float4 acc = make_float4(0.0f, 0.0f, 0.0f, 0.0f);
        for (int bb = chunk; bb < NBLK_B; bb += 16) {
            const float* p = &g_part[(size_t)bb * D + q * 4];
            acc.x += __ldcg(p + 0);
            acc.y += __ldcg(p + 1);
            acc.z += __ldcg(p + 2);
            acc.w += __ldcg(p + 3);
        }
        cpart[chunk][q * 4 + 0] = acc.x;
        cpart[chunk][q * 4 + 1] = acc.y;
        cpart[chunk][q * 4 + 2] = acc.z;
        cpart[chunk][q * 4 + 3] = acc.w;
    }
    if (warp == 0) {
        float sm = 0.0f;
        for (int bb = lane; bb < NBLK_B; bb += 32) sm += __ldcg(&g_psum[bb]);
        #pragma unroll
        for (int o = 16; o > 0; o >>= 1)
            sm += __shfl_xor_sync(0xffffffffu, sm, o);
        if (lane == 0) sh_tot = sm;
    }
    __syncthreads();

    if (tid < D) {
        float s = 0.0f;
        #pragma unroll
        for (int c = 0; c < 16; c++) s += cpart[c][tid];
        sh_lhs[tid] = s / sh_tot;
    }
    __syncthreads();

    for (int j = tid; j < OUT_ROWS * D; j += 512)
        out[j] = sh_lhs[j & (D - 1)];

    if (tid == 0) g_counter = 0;   // reset for next graph replay
}

extern "C" void kernel_launch(void* const* d_in, const int* in_sizes, int n_in,
                              void* d_out, int out_size) {
    const int*   xs    = (const int*)d_in[0];
    const int*   mems  = (const int*)d_in[1];
    const int*   ys    = (const int*)d_in[2];
    const int*   cands = (const int*)d_in[3];
    const float* lt    = (const float*)d_in[4];
    const float* freqs = (const float*)d_in[5];
    float* out = (float*)d_out;

    encode_all<<<2 + M_MEM + C_N, 512>>>(xs, mems, ys, cands, lt, freqs, out);
    sims_finalize_kernel<<<NBLK_B, 512>>>(out);
}

// round 10
// speedup vs baseline: 1.8466x; 1.0322x over previous
#include <cuda_runtime.h>

#define V_VOCAB 500000
#define D 128
#define M_MEM 1000
#define L_MEM 64
#define L_X 64
#define C_N 100
#define L_C 32
#define L_Y 32
#define N_MEMS (M_MEM + 1)            /* 1001: row0=xs, rows1..1000=mems */
#define OUT_ROWS (1 + C_N)            /* 101 */
#define NBLK_B 63                     /* ceil(1001/16) */
#define MAX_NORM 10.0f
#define RENORM_EPS 1e-7f
#define COS_EPS 1e-8f

// row 0 = xs encoding, rows 1..1000 = mems encodings. 512.5 KB.
__device__ float g_enc[(size_t)N_MEMS * D];
// per-block partials from kernel B
__device__ float g_part[(size_t)NBLK_B * D];
__device__ float g_psum[NBLK_B];
__device__ int   g_counter;          // zero-init; reset by finalizing block

// ---------------------------------------------------------------------------
// Encode body, L compile-time. 512 threads = 16 warps; warp w owns tokens
// w, w+16, ... All gathers in flight; norm reduces interleaved.
// ---------------------------------------------------------------------------
template <int L>
__device__ __forceinline__ void encode_body(
    const int* __restrict__ seq,
    const float* __restrict__ lt, const float* __restrict__ freqs,
    float* __restrict__ dst)
{
    constexpr int NW = 16;
    constexpr int NT = L / NW;

    __shared__ int   sh_idx[L];
    __shared__ float sh_w[L];
    __shared__ float sh_wred[2];
    __shared__ float sh_acc[NW][D];

    int tid  = threadIdx.x;
    int warp = tid >> 5;
    int lane = tid & 31;

    if (tid < L) {
        int idx = seq[tid];
        sh_idx[tid] = idx;
        float f = freqs[idx];
        sh_w[tid] = f;
        float ws = f * f;
        #pragma unroll
        for (int o = 16; o > 0; o >>= 1)
            ws += __shfl_xor_sync(0xffffffffu, ws, o);
        if (lane == 0) sh_wred[warp] = ws;
    }
    __syncthreads();

    float inv_wnorm = rsqrtf((L > 32) ? (sh_wred[0] + sh_wred[1]) : sh_wred[0]);

    float4 e[NT];
    int    tok[NT];
    #pragma unroll
    for (int k = 0; k < NT; k++) {
        tok[k] = warp + NW * k;
        int idx = sh_idx[tok[k]];
        e[k] = *reinterpret_cast<const float4*>(lt + (size_t)idx * D + lane * 4);
    }

    float sq[NT];
    #pragma unroll
    for (int k = 0; k < NT; k++)
        sq[k] = e[k].x * e[k].x + e[k].y * e[k].y
              + e[k].z * e[k].z + e[k].w * e[k].w;
    #pragma unroll
    for (int o = 16; o > 0; o >>= 1) {
        #pragma unroll
        for (int k = 0; k < NT; k++)
            sq[k] += __shfl_xor_sync(0xffffffffu, sq[k], o);
    }

    float4 acc = make_float4(0.0f, 0.0f, 0.0f, 0.0f);
    #pragma unroll
    for (int k = 0; k < NT; k++) {
        float n = sqrtf(sq[k]);
        float scale = (n > MAX_NORM) ? (MAX_NORM / (n + RENORM_EPS)) : 1.0f;
        float wl = sh_w[tok[k]] * inv_wnorm * scale;
        acc.x += wl * e[k].x;
        acc.y += wl * e[k].y;
        acc.z += wl * e[k].z;
        acc.w += wl * e[k].w;
    }

    sh_acc[warp][lane * 4 + 0] = acc.x;
    sh_acc[warp][lane * 4 + 1] = acc.y;
    sh_acc[warp][lane * 4 + 2] = acc.z;
    sh_acc[warp][lane * 4 + 3] = acc.w;
    __syncthreads();

    if (tid < D) {
        float s = 0.0f;
        #pragma unroll
        for (int w = 0; w < NW; w++) s += sh_acc[w][tid];
        dst[tid] = s;
    }
}

// ---------------------------------------------------------------------------
// Kernel A: encode all 1102 sequences (fully independent). Each block fires
// the PDL trigger after its final stores so kernel B can roll out early.
// ---------------------------------------------------------------------------
__global__ __launch_bounds__(512) void encode_all(
    const int* __restrict__ xs, const int* __restrict__ mems,
    const int* __restrict__ ys, const int* __restrict__ cands,
    const float* __restrict__ lt, const float* __restrict__ freqs,
    float* __restrict__ out)
{
    int b = blockIdx.x;
    if (b == 0) {
        encode_body<L_X>(xs, lt, freqs, g_enc);
    } else if (b <= M_MEM) {
        encode_body<L_MEM>(mems + (size_t)(b - 1) * L_MEM, lt, freqs,
                           g_enc + (size_t)b * D);
    } else if (b == M_MEM + 1) {
        encode_body<L_Y>(ys, lt, freqs, out + (size_t)OUT_ROWS * D);
    } else {
        int c = b - M_MEM - 2;
        encode_body<L_C>(cands + (size_t)c * L_C, lt, freqs,
                         out + (size_t)(OUT_ROWS + 1 + c) * D);
    }
#if __CUDA_ARCH__ >= 900
    cudaTriggerProgrammaticLaunchCompletion();
#endif
}

// ---------------------------------------------------------------------------
// Kernel B: sims + exp + per-block partials; the LAST block (atomic counter)
// reduces the 63 partials in fixed order and writes the broadcast output.
// 63 blocks x 16 warps, one row per warp. Launched with PDL: CTAs roll out
// during A's tail and wait at cudaGridDependencySynchronize().
// ---------------------------------------------------------------------------
__global__ __launch_bounds__(512) void sims_finalize_kernel(float* __restrict__ out)
{
#if __CUDA_ARCH__ >= 900
    cudaGridDependencySynchronize();
#endif

    __shared__ float sh_part[16][D];
    __shared__ float sh_exp[16];

    int tid  = threadIdx.x;
    int warp = tid >> 5;
    int lane = tid & 31;
    int i = blockIdx.x * 16 + warp;
    bool valid = (i < N_MEMS);
    int r = valid ? ((i < M_MEM) ? (i + 1) : 0) : 0;

    float4 x = *reinterpret_cast<const float4*>(&g_enc[lane * 4]);
    float4 e = *reinterpret_cast<const float4*>(&g_enc[(size_t)r * D + lane * 4]);

    float dot = e.x * x.x + e.y * x.y + e.z * x.z + e.w * x.w;
    float esq = e.x * e.x + e.y * e.y + e.z * e.z + e.w * e.w;
    float xsq = x.x * x.x + x.y * x.y + x.z * x.z + x.w * x.w;
    #pragma unroll
    for (int o = 16; o > 0; o >>= 1) {
        dot += __shfl_xor_sync(0xffffffffu, dot, o);
        esq += __shfl_xor_sync(0xffffffffu, esq, o);
        xsq += __shfl_xor_sync(0xffffffffu, xsq, o);
    }
    float nx = fmaxf(sqrtf(xsq), COS_EPS);
    float nm = fmaxf(sqrtf(esq), COS_EPS);
    float ex = valid ? expf(dot / (nx * nm)) : 0.0f;

    sh_part[warp][lane * 4 + 0] = ex * e.x;
    sh_part[warp][lane * 4 + 1] = ex * e.y;
    sh_part[warp][lane * 4 + 2] = ex * e.z;
    sh_part[warp][lane * 4 + 3] = ex * e.w;
    if (lane == 0) sh_exp[warp] = ex;
    __syncthreads();

    if (tid < D) {
        float s = 0.0f;
        #pragma unroll
        for (int w = 0; w < 16; w++) s += sh_part[w][tid];
        g_part[(size_t)blockIdx.x * D + tid] = s;
    }
    if (tid == 0) {
        float s = 0.0f;
        #pragma unroll
        for (int w = 0; w < 16; w++) s += sh_exp[w];
        g_psum[blockIdx.x] = s;
    }
    __threadfence();
    __syncthreads();

    // --- last block finalizes ---
    __shared__ int sh_last;
    if (tid == 0) {
        int old = atomicAdd(&g_counter, 1);
        sh_last = (old == NBLK_B - 1) ? 1 : 0;
    }
    __syncthreads();
    if (!sh_last) return;
    __threadfence();

    __shared__ float cpart[16][D];
    __shared__ float sh_tot;
    __shared__ float sh_lhs[D];

    {
        int q = tid & 31;          // float4 column
        int chunk = tid >> 5;      // 0..15
        float4 acc = make_float4(0.0f, 0.0f, 0.0f, 0.0f);
        for (int bb = chunk; bb < NBLK_B; bb += 16) {
            const float* p = &g_part[(size_t)bb * D + q * 4];
            acc.x += __ldcg(p + 0);
            acc.y += __ldcg(p + 1);
            acc.z += __ldcg(p + 2);
            acc.w += __ldcg(p + 3);
        }
        cpart[chunk][q * 4 + 0] = acc.x;
        cpart[chunk][q * 4 + 1] = acc.y;
        cpart[chunk][q * 4 + 2] = acc.z;
        cpart[chunk][q * 4 + 3] = acc.w;
    }
    if (warp == 0) {
        float sm = 0.0f;
        for (int bb = lane; bb < NBLK_B; bb += 32) sm += __ldcg(&g_psum[bb]);
        #pragma unroll
        for (int o = 16; o > 0; o >>= 1)
            sm += __shfl_xor_sync(0xffffffffu, sm, o);
        if (lane == 0) sh_tot = sm;
    }
    __syncthreads();

    if (tid < D) {
        float s = 0.0f;
        #pragma unroll
        for (int c = 0; c < 16; c++) s += cpart[c][tid];
        sh_lhs[tid] = s / sh_tot;
    }
    __syncthreads();

    for (int j = tid; j < OUT_ROWS * D; j += 512)
        out[j] = sh_lhs[j & (D - 1)];

    if (tid == 0) g_counter = 0;   // reset for next graph replay
}

extern "C" void kernel_launch(void* const* d_in, const int* in_sizes, int n_in,
                              void* d_out, int out_size) {
    const int*   xs    = (const int*)d_in[0];
    const int*   mems  = (const int*)d_in[1];
    const int*   ys    = (const int*)d_in[2];
    const int*   cands = (const int*)d_in[3];
    const float* lt    = (const float*)d_in[4];
    const float* freqs = (const float*)d_in[5];
    float* out = (float*)d_out;

    encode_all<<<2 + M_MEM + C_N, 512>>>(xs, mems, ys, cands, lt, freqs, out);

    // Kernel B with programmatic dependent launch: overlaps its CTA rollout
    // with A's tail; correctness guarded by cudaGridDependencySynchronize().
    cudaLaunchConfig_t cfg = {};
    cfg.gridDim  = dim3(NBLK_B, 1, 1);
    cfg.blockDim = dim3(512, 1, 1);
    cfg.dynamicSmemBytes = 0;
    cfg.stream = 0;
    cudaLaunchAttribute attrs[1];
    attrs[0].id = cudaLaunchAttributeProgrammaticStreamSerialization;
    attrs[0].val.programmaticStreamSerializationAllowed = 1;
    cfg.attrs = attrs;
    cfg.numAttrs = 1;
    cudaError_t err = cudaLaunchKernelEx(&cfg, sims_finalize_kernel, out);
    if (err != cudaSuccess) {
        // Fallback: plain launch (still correct, just without overlap)
        sims_finalize_kernel<<<NBLK_B, 512>>>(out);
    }
}

// round 11
// speedup vs baseline: 1.8501x; 1.0019x over previous
#include <cuda_runtime.h>

#define V_VOCAB 500000
#define D 128
#define M_MEM 1000
#define L_MEM 64
#define L_X 64
#define C_N 100
#define L_C 32
#define L_Y 32
#define N_MEMS (M_MEM + 1)            /* 1001: row0=xs, rows1..1000=mems */
#define OUT_ROWS (1 + C_N)            /* 101 */
#define NBLK_B 32                     /* ceil(1001/32) */
#define MAX_NORM 10.0f
#define RENORM_EPS 1e-7f
#define COS_EPS 1e-8f

// row 0 = xs encoding, rows 1..1000 = mems encodings. 512.5 KB.
__device__ float g_enc[(size_t)N_MEMS * D];
// per-block partials from kernel B
__device__ float g_part[(size_t)NBLK_B * D];
__device__ float g_psum[NBLK_B];
__device__ int   g_counter;          // zero-init; reset by finalizing block

// ---------------------------------------------------------------------------
// Encode body, L compile-time. 512 threads = 16 warps; warp w owns tokens
// w, w+16, ... All gathers in flight; norm reduces interleaved.
// ---------------------------------------------------------------------------
template <int L>
__device__ __forceinline__ void encode_body(
    const int* __restrict__ seq,
    const float* __restrict__ lt, const float* __restrict__ freqs,
    float* __restrict__ dst)
{
    constexpr int NW = 16;
    constexpr int NT = L / NW;

    __shared__ int   sh_idx[L];
    __shared__ float sh_w[L];
    __shared__ float sh_wred[2];
    __shared__ float sh_acc[NW][D];

    int tid  = threadIdx.x;
    int warp = tid >> 5;
    int lane = tid & 31;

    if (tid < L) {
        int idx = seq[tid];
        sh_idx[tid] = idx;
        float f = freqs[idx];
        sh_w[tid] = f;
        float ws = f * f;
        #pragma unroll
        for (int o = 16; o > 0; o >>= 1)
            ws += __shfl_xor_sync(0xffffffffu, ws, o);
        if (lane == 0) sh_wred[warp] = ws;
    }
    __syncthreads();

    float inv_wnorm = rsqrtf((L > 32) ? (sh_wred[0] + sh_wred[1]) : sh_wred[0]);

    float4 e[NT];
    int    tok[NT];
    #pragma unroll
    for (int k = 0; k < NT; k++) {
        tok[k] = warp + NW * k;
        int idx = sh_idx[tok[k]];
        e[k] = *reinterpret_cast<const float4*>(lt + (size_t)idx * D + lane * 4);
    }

    float sq[NT];
    #pragma unroll
    for (int k = 0; k < NT; k++)
        sq[k] = e[k].x * e[k].x + e[k].y * e[k].y
              + e[k].z * e[k].z + e[k].w * e[k].w;
    #pragma unroll
    for (int o = 16; o > 0; o >>= 1) {
        #pragma unroll
        for (int k = 0; k < NT; k++)
            sq[k] += __shfl_xor_sync(0xffffffffu, sq[k], o);
    }

    float4 acc = make_float4(0.0f, 0.0f, 0.0f, 0.0f);
    #pragma unroll
    for (int k = 0; k < NT; k++) {
        float n = sqrtf(sq[k]);
        float scale = (n > MAX_NORM) ? (MAX_NORM / (n + RENORM_EPS)) : 1.0f;
        float wl = sh_w[tok[k]] * inv_wnorm * scale;
        acc.x += wl * e[k].x;
        acc.y += wl * e[k].y;
        acc.z += wl * e[k].z;
        acc.w += wl * e[k].w;
    }

    sh_acc[warp][lane * 4 + 0] = acc.x;
    sh_acc[warp][lane * 4 + 1] = acc.y;
    sh_acc[warp][lane * 4 + 2] = acc.z;
    sh_acc[warp][lane * 4 + 3] = acc.w;
    __syncthreads();

    if (tid < D) {
        float s = 0.0f;
        #pragma unroll
        for (int w = 0; w < NW; w++) s += sh_acc[w][tid];
        dst[tid] = s;
    }
}

// ---------------------------------------------------------------------------
// Kernel A: encode all 1102 sequences (fully independent). Each block fires
// the PDL trigger after its final stores so kernel B can roll out early.
// ---------------------------------------------------------------------------
__global__ __launch_bounds__(512) void encode_all(
    const int* __restrict__ xs, const int* __restrict__ mems,
    const int* __restrict__ ys, const int* __restrict__ cands,
    const float* __restrict__ lt, const float* __restrict__ freqs,
    float* __restrict__ out)
{
    int b = blockIdx.x;
    if (b == 0) {
        encode_body<L_X>(xs, lt, freqs, g_enc);
    } else if (b <= M_MEM) {
        encode_body<L_MEM>(mems + (size_t)(b - 1) * L_MEM, lt, freqs,
                           g_enc + (size_t)b * D);
    } else if (b == M_MEM + 1) {
        encode_body<L_Y>(ys, lt, freqs, out + (size_t)OUT_ROWS * D);
    } else {
        int c = b - M_MEM - 2;
        encode_body<L_C>(cands + (size_t)c * L_C, lt, freqs,
                         out + (size_t)(OUT_ROWS + 1 + c) * D);
    }
#if __CUDA_ARCH__ >= 900
    cudaTriggerProgrammaticLaunchCompletion();
#endif
}

// ---------------------------------------------------------------------------
// Kernel B: sims + exp + per-block partials; the LAST block (atomic counter)
// reduces the 32 partials in fixed order and writes the broadcast output.
// 32 blocks x 32 warps, one row per warp, PDL-launched.
// exp needs no max shift: cosines are in [-1,1].
// ---------------------------------------------------------------------------
__global__ __launch_bounds__(1024) void sims_finalize_kernel(float* __restrict__ out)
{
#if __CUDA_ARCH__ >= 900
    cudaGridDependencySynchronize();
#endif

    __shared__ float sh_part[32][D];
    __shared__ float sh_exp[32];

    int tid  = threadIdx.x;
    int warp = tid >> 5;
    int lane = tid & 31;
    int i = blockIdx.x * 32 + warp;
    bool valid = (i < N_MEMS);
    int r = valid ? ((i < M_MEM) ? (i + 1) : 0) : 0;

    float4 x = *reinterpret_cast<const float4*>(&g_enc[lane * 4]);
    float4 e = *reinterpret_cast<const float4*>(&g_enc[(size_t)r * D + lane * 4]);

    float dot = e.x * x.x + e.y * x.y + e.z * x.z + e.w * x.w;
    float esq = e.x * e.x + e.y * e.y + e.z * e.z + e.w * e.w;
    float xsq = x.x * x.x + x.y * x.y + x.z * x.z + x.w * x.w;
    #pragma unroll
    for (int o = 16; o > 0; o >>= 1) {
        dot += __shfl_xor_sync(0xffffffffu, dot, o);
        esq += __shfl_xor_sync(0xffffffffu, esq, o);
        xsq += __shfl_xor_sync(0xffffffffu, xsq, o);
    }
    float nx = fmaxf(sqrtf(xsq), COS_EPS);
    float nm = fmaxf(sqrtf(esq), COS_EPS);
    float ex = valid ? expf(dot / (nx * nm)) : 0.0f;

    sh_part[warp][lane * 4 + 0] = ex * e.x;
    sh_part[warp][lane * 4 + 1] = ex * e.y;
    sh_part[warp][lane * 4 + 2] = ex * e.z;
    sh_part[warp][lane * 4 + 3] = ex * e.w;
    if (lane == 0) sh_exp[warp] = ex;
    __syncthreads();

    if (tid < D) {
        float s = 0.0f;
        #pragma unroll
        for (int w = 0; w < 32; w++) s += sh_part[w][tid];
        g_part[(size_t)blockIdx.x * D + tid] = s;
    }
    if (tid == 0) {
        float s = 0.0f;
        #pragma unroll
        for (int w = 0; w < 32; w++) s += sh_exp[w];
        g_psum[blockIdx.x] = s;
    }
    __threadfence();
    __syncthreads();

    // --- last block finalizes ---
    __shared__ int sh_last;
    if (tid == 0) {
        int old = atomicAdd(&g_counter, 1);
        sh_last = (old == NBLK_B - 1) ? 1 : 0;
    }
    __syncthreads();
    if (!sh_last) return;
    __threadfence();

    __shared__ float cpart[8][D];
    __shared__ float sh_tot;
    __shared__ float sh_lhs[D];

    {
        int q = tid & 31;          // float4 column
        int chunk = tid >> 5;      // 0..31 -> use 0..7, 4 blocks each
        if (chunk < 8) {
            float4 acc = make_float4(0.0f, 0.0f, 0.0f, 0.0f);
            #pragma unroll
            for (int k = 0; k < 4; k++) {
                int bb = chunk * 4 + k;
                const float* p = &g_part[(size_t)bb * D + q * 4];
                acc.x += __ldcg(p + 0);
                acc.y += __ldcg(p + 1);
                acc.z += __ldcg(p + 2);
                acc.w += __ldcg(p + 3);
            }
            cpart[chunk][q * 4 + 0] = acc.x;
            cpart[chunk][q * 4 + 1] = acc.y;
            cpart[chunk][q * 4 + 2] = acc.z;
            cpart[chunk][q * 4 + 3] = acc.w;
        }
    }
    if (warp == 0) {
        float sm = (lane < NBLK_B) ? __ldcg(&g_psum[lane]) : 0.0f;
        #pragma unroll
        for (int o = 16; o > 0; o >>= 1)
            sm += __shfl_xor_sync(0xffffffffu, sm, o);
        if (lane == 0) sh_tot = sm;
    }
    __syncthreads();

    if (tid < D) {
        float s = 0.0f;
        #pragma unroll
        for (int c = 0; c < 8; c++) s += cpart[c][tid];
        sh_lhs[tid] = s / sh_tot;
    }
    __syncthreads();

    for (int j = tid; j < OUT_ROWS * D; j += 1024)
        out[j] = sh_lhs[j & (D - 1)];

    if (tid == 0) g_counter = 0;   // reset for next graph replay
}

extern "C" void kernel_launch(void* const* d_in, const int* in_sizes, int n_in,
                              void* d_out, int out_size) {
    const int*   xs    = (const int*)d_in[0];
    const int*   mems  = (const int*)d_in[1];
    const int*   ys    = (const int*)d_in[2];
    const int*   cands = (const int*)d_in[3];
    const float* lt    = (const float*)d_in[4];
    const float* freqs = (const float*)d_in[5];
    float* out = (float*)d_out;

    encode_all<<<2 + M_MEM + C_N, 512>>>(xs, mems, ys, cands, lt, freqs, out);

    // Kernel B with programmatic dependent launch: overlaps its CTA rollout
    // with A's tail; correctness guarded by cudaGridDependencySynchronize().
    cudaLaunchConfig_t cfg = {};
    cfg.gridDim  = dim3(NBLK_B, 1, 1);
    cfg.blockDim = dim3(1024, 1, 1);
    cfg.dynamicSmemBytes = 0;
    cfg.stream = 0;
    cudaLaunchAttribute attrs[1];
    attrs[0].id = cudaLaunchAttributeProgrammaticStreamSerialization;
    attrs[0].val.programmaticStreamSerializationAllowed = 1;
    cfg.attrs = attrs;
    cfg.numAttrs = 1;
    cudaError_t err = cudaLaunchKernelEx(&cfg, sims_finalize_kernel, out);
    if (err != cudaSuccess) {
        // Fallback: plain launch (still correct, just without overlap)
        sims_finalize_kernel<<<NBLK_B, 1024>>>(out);
    }
}

// round 12
// speedup vs baseline: 1.8536x; 1.0019x over previous
#include <cuda_runtime.h>

#define V_VOCAB 500000
#define D 128
#define M_MEM 1000
#define L_MEM 64
#define L_X 64
#define C_N 100
#define L_C 32
#define L_Y 32
#define N_MEMS (M_MEM + 1)            /* 1001: row0=xs, rows1..1000=mems */
#define OUT_ROWS (1 + C_N)            /* 101 */
#define NBLK_B 32                     /* ceil(1001/32) */
#define MAX_NORM 10.0f
#define RENORM_EPS 1e-7f
#define COS_EPS 1e-8f

// row 0 = xs encoding, rows 1..1000 = mems encodings. 512.5 KB.
__device__ float g_enc[(size_t)N_MEMS * D];
// per-block partials from kernel B
__device__ float g_part[(size_t)NBLK_B * D];
__device__ float g_psum[NBLK_B];
__device__ int   g_counter;          // zero-init; reset by finalizing block

// ---------------------------------------------------------------------------
// Encode body, L compile-time. 512 threads = 16 warps; warp w owns tokens
// w, w+16, ... Token ids and freqs are loaded directly per-warp (broadcast
// LDGs) so the row gathers issue with no shared staging / no leading sync.
// The tf-idf 1/||w|| factor is uniform, so it is applied once at the final
// write, keeping the w-norm reduction off the critical path.
// ---------------------------------------------------------------------------
template <int L>
__device__ __forceinline__ void encode_body(
    const int* __restrict__ seq,
    const float* __restrict__ lt, const float* __restrict__ freqs,
    float* __restrict__ dst)
{
    constexpr int NW = 16;
    constexpr int NT = L / NW;

    __shared__ float sh_wsq[NW];
    __shared__ float sh_acc[NW][D];

    int tid  = threadIdx.x;
    int warp = tid >> 5;
    int lane = tid & 31;

    // token ids for this warp (broadcast loads, all lanes same address)
    int idx[NT];
    #pragma unroll
    for (int k = 0; k < NT; k++)
        idx[k] = seq[warp + NW * k];

    // issue the big row gathers immediately (streaming: ~single touch)
    float4 e[NT];
    #pragma unroll
    for (int k = 0; k < NT; k++)
        e[k] = __ldcs(reinterpret_cast<const float4*>(
                   lt + (size_t)idx[k] * D) + lane);

    // freqs (broadcast loads) — overlaps the row gathers
    float f[NT];
    #pragma unroll
    for (int k = 0; k < NT; k++)
        f[k] = freqs[idx[k]];

    // per-warp w-sumsq (uniform across lanes; no reduce needed)
    {
        float ws = 0.0f;
        #pragma unroll
        for (int k = 0; k < NT; k++) ws += f[k] * f[k];
        if (lane == 0) sh_wsq[warp] = ws;
    }

    // interleaved per-token norm reduces
    float sq[NT];
    #pragma unroll
    for (int k = 0; k < NT; k++)
        sq[k] = e[k].x * e[k].x + e[k].y * e[k].y
              + e[k].z * e[k].z + e[k].w * e[k].w;
    #pragma unroll
    for (int o = 16; o > 0; o >>= 1) {
        #pragma unroll
        for (int k = 0; k < NT; k++)
            sq[k] += __shfl_xor_sync(0xffffffffu, sq[k], o);
    }

    // unscaled accumulation (inv_wnorm applied at the end)
    float4 acc = make_float4(0.0f, 0.0f, 0.0f, 0.0f);
    #pragma unroll
    for (int k = 0; k < NT; k++) {
        float n = sqrtf(sq[k]);
        float scale = (n > MAX_NORM) ? (MAX_NORM / (n + RENORM_EPS)) : 1.0f;
        float wl = f[k] * scale;
        acc.x += wl * e[k].x;
        acc.y += wl * e[k].y;
        acc.z += wl * e[k].z;
        acc.w += wl * e[k].w;
    }

    sh_acc[warp][lane * 4 + 0] = acc.x;
    sh_acc[warp][lane * 4 + 1] = acc.y;
    sh_acc[warp][lane * 4 + 2] = acc.z;
    sh_acc[warp][lane * 4 + 3] = acc.w;
    __syncthreads();

    if (tid < D) {
        float wsq = 0.0f;
        #pragma unroll
        for (int w = 0; w < NW; w++) wsq += sh_wsq[w];
        float s = 0.0f;
        #pragma unroll
        for (int w = 0; w < NW; w++) s += sh_acc[w][tid];
        dst[tid] = s * rsqrtf(wsq);
    }
}

// ---------------------------------------------------------------------------
// Kernel A: encode all 1102 sequences (fully independent). Each block fires
// the PDL trigger after its final stores so kernel B can roll out early.
// ---------------------------------------------------------------------------
__global__ __launch_bounds__(512) void encode_all(
    const int* __restrict__ xs, const int* __restrict__ mems,
    const int* __restrict__ ys, const int* __restrict__ cands,
    const float* __restrict__ lt, const float* __restrict__ freqs,
    float* __restrict__ out)
{
    int b = blockIdx.x;
    if (b == 0) {
        encode_body<L_X>(xs, lt, freqs, g_enc);
    } else if (b <= M_MEM) {
        encode_body<L_MEM>(mems + (size_t)(b - 1) * L_MEM, lt, freqs,
                           g_enc + (size_t)b * D);
    } else if (b == M_MEM + 1) {
        encode_body<L_Y>(ys, lt, freqs, out + (size_t)OUT_ROWS * D);
    } else {
        int c = b - M_MEM - 2;
        encode_body<L_C>(cands + (size_t)c * L_C, lt, freqs,
                         out + (size_t)(OUT_ROWS + 1 + c) * D);
    }
#if __CUDA_ARCH__ >= 900
    cudaTriggerProgrammaticLaunchCompletion();
#endif
}

// ---------------------------------------------------------------------------
// Kernel B: sims + exp + per-block partials; the LAST block (atomic counter)
// reduces the 32 partials in fixed order and writes the broadcast output.
// 32 blocks x 32 warps, one row per warp, PDL-launched.
// exp needs no max shift: cosines are in [-1,1].
// ---------------------------------------------------------------------------
__global__ __launch_bounds__(1024) void sims_finalize_kernel(float* __restrict__ out)
{
#if __CUDA_ARCH__ >= 900
    cudaGridDependencySynchronize();
#endif

    __shared__ float sh_part[32][D];
    __shared__ float sh_exp[32];

    int tid  = threadIdx.x;
    int warp = tid >> 5;
    int lane = tid & 31;
    int i = blockIdx.x * 32 + warp;
    bool valid = (i < N_MEMS);
    int r = valid ? ((i < M_MEM) ? (i + 1) : 0) : 0;

    float4 x = *reinterpret_cast<const float4*>(&g_enc[lane * 4]);
    float4 e = *reinterpret_cast<const float4*>(&g_enc[(size_t)r * D + lane * 4]);

    float dot = e.x * x.x + e.y * x.y + e.z * x.z + e.w * x.w;
    float esq = e.x * e.x + e.y * e.y + e.z * e.z + e.w * e.w;
    float xsq = x.x * x.x + x.y * x.y + x.z * x.z + x.w * x.w;
    #pragma unroll
    for (int o = 16; o > 0; o >>= 1) {
        dot += __shfl_xor_sync(0xffffffffu, dot, o);
        esq += __shfl_xor_sync(0xffffffffu, esq, o);
        xsq += __shfl_xor_sync(0xffffffffu, xsq, o);
    }
    float nx = fmaxf(sqrtf(xsq), COS_EPS);
    float nm = fmaxf(sqrtf(esq), COS_EPS);
    float ex = valid ? expf(dot / (nx * nm)) : 0.0f;

    sh_part[warp][lane * 4 + 0] = ex * e.x;
    sh_part[warp][lane * 4 + 1] = ex * e.y;
    sh_part[warp][lane * 4 + 2] = ex * e.z;
    sh_part[warp][lane * 4 + 3] = ex * e.w;
    if (lane == 0) sh_exp[warp] = ex;
    __syncthreads();

    if (tid < D) {
        float s = 0.0f;
        #pragma unroll
        for (int w = 0; w < 32; w++) s += sh_part[w][tid];
        g_part[(size_t)blockIdx.x * D + tid] = s;
    }
    if (tid == 0) {
        float s = 0.0f;
        #pragma unroll
        for (int w = 0; w < 32; w++) s += sh_exp[w];
        g_psum[blockIdx.x] = s;
    }
    __threadfence();
    __syncthreads();

    // --- last block finalizes ---
    __shared__ int sh_last;
    if (tid == 0) {
        int old = atomicAdd(&g_counter, 1);
        sh_last = (old == NBLK_B - 1) ? 1 : 0;
    }
    __syncthreads();
    if (!sh_last) return;
    __threadfence();

    __shared__ float cpart[8][D];
    __shared__ float sh_tot;
    __shared__ float sh_lhs[D];

    {
        int q = tid & 31;          // float4 column
        int chunk = tid >> 5;      // 0..31 -> use 0..7, 4 blocks each
        if (chunk < 8) {
            float4 acc = make_float4(0.0f, 0.0f, 0.0f, 0.0f);
            #pragma unroll
            for (int k = 0; k < 4; k++) {
                int bb = chunk * 4 + k;
                const float* p = &g_part[(size_t)bb * D + q * 4];
                acc.x += __ldcg(p + 0);
                acc.y += __ldcg(p + 1);
                acc.z += __ldcg(p + 2);
                acc.w += __ldcg(p + 3);
            }
            cpart[chunk][q * 4 + 0] = acc.x;
            cpart[chunk][q * 4 + 1] = acc.y;
            cpart[chunk][q * 4 + 2] = acc.z;
            cpart[chunk][q * 4 + 3] = acc.w;
        }
    }
    if (warp == 0) {
        float sm = (lane < NBLK_B) ? __ldcg(&g_psum[lane]) : 0.0f;
        #pragma unroll
        for (int o = 16; o > 0; o >>= 1)
            sm += __shfl_xor_sync(0xffffffffu, sm, o);
        if (lane == 0) sh_tot = sm;
    }
    __syncthreads();

    if (tid < D) {
        float s = 0.0f;
        #pragma unroll
        for (int c = 0; c < 8; c++) s += cpart[c][tid];
        sh_lhs[tid] = s / sh_tot;
    }
    __syncthreads();

    for (int j = tid; j < OUT_ROWS * D; j += 1024)
        out[j] = sh_lhs[j & (D - 1)];

    if (tid == 0) g_counter = 0;   // reset for next graph replay
}

extern "C" void kernel_launch(void* const* d_in, const int* in_sizes, int n_in,
                              void* d_out, int out_size) {
    const int*   xs    = (const int*)d_in[0];
    const int*   mems  = (const int*)d_in[1];
    const int*   ys    = (const int*)d_in[2];
    const int*   cands = (const int*)d_in[3];
    const float* lt    = (const float*)d_in[4];
    const float* freqs = (const float*)d_in[5];
    float* out = (float*)d_out;

    encode_all<<<2 + M_MEM + C_N, 512>>>(xs, mems, ys, cands, lt, freqs, out);

    // Kernel B with programmatic dependent launch: overlaps its CTA rollout
    // with A's tail; correctness guarded by cudaGridDependencySynchronize().
    cudaLaunchConfig_t cfg = {};
    cfg.gridDim  = dim3(NBLK_B, 1, 1);
    cfg.blockDim = dim3(1024, 1, 1);
    cfg.dynamicSmemBytes = 0;
    cfg.stream = 0;
    cudaLaunchAttribute attrs[1];
    attrs[0].id = cudaLaunchAttributeProgrammaticStreamSerialization;
    attrs[0].val.programmaticStreamSerializationAllowed = 1;
    cfg.attrs = attrs;
    cfg.numAttrs = 1;
    cudaError_t err = cudaLaunchKernelEx(&cfg, sims_finalize_kernel, out);
    if (err != cudaSuccess) {
        // Fallback: plain launch (still correct, just without overlap)
        sims_finalize_kernel<<<NBLK_B, 1024>>>(out);
    }
}